// round 14
// baseline (speedup 1.0000x reference)
#include <cuda_runtime.h>
#include <math.h>
#include <float.h>

#define NB 32
#define NQ 900
#define NT 300
#define NC 256

#define W_CLASS 1.0f
#define W_BBOX  5.0f
#define W_GIOU  2.0f
#define W_CUTIN 2.0f

#define SCALE_F 17179869184.0f      // 2^34
#define PBIAS   (1ULL << 62)
#define BIGKEY  (1ULL << 45)
#define AUC_CAP 24
#define LSA_THREADS 512
#define LSA_WARPS   16

// Scratch (allocation-free rule: __device__ globals)
__device__ float g_CT[(size_t)NB * NT * NQ];          // transposed cost [b][t][q]
__device__ float g_rmax[NB * NQ];
__device__ float g_rsum[NB * NQ];
__device__ unsigned long long g_rowmin[NB * NT];      // packed (fix<<11|col)+bias

__device__ __forceinline__ long long f2fix(float x) {
    return __float2ll_rn(x * SCALE_F);
}

// ---------------------------------------------------------------------------
// Kernel 1: softmax stats (max, sumexp) per (b,q). 1 warp/row, float4 loads.
// Also re-initializes g_rowmin every launch (graph replay safety).
// ---------------------------------------------------------------------------
__global__ void softmax_stats_kernel(const float* __restrict__ logits) {
    int gtid = blockIdx.x * blockDim.x + threadIdx.x;
    if (gtid < NB * NT) g_rowmin[gtid] = ~0ULL;

    int warp = gtid >> 5;
    int lane = threadIdx.x & 31;
    if (warp >= NB * NQ) return;
    const float4* row4 = reinterpret_cast<const float4*>(logits + (size_t)warp * NC);
    float4 a = row4[lane];
    float4 b = row4[lane + 32];
    float m = fmaxf(fmaxf(fmaxf(a.x, a.y), fmaxf(a.z, a.w)),
                    fmaxf(fmaxf(b.x, b.y), fmaxf(b.z, b.w)));
#pragma unroll
    for (int o = 16; o; o >>= 1) m = fmaxf(m, __shfl_xor_sync(0xffffffffu, m, o));
    float s = expf(a.x - m) + expf(a.y - m) + expf(a.z - m) + expf(a.w - m)
            + expf(b.x - m) + expf(b.y - m) + expf(b.z - m) + expf(b.w - m);
#pragma unroll
    for (int o = 16; o; o >>= 1) s += __shfl_xor_sync(0xffffffffu, s, o);
    if (lane == 0) { g_rmax[warp] = m; g_rsum[warp] = s; }
}

// ---------------------------------------------------------------------------
// Kernel 2 (fused): cost matrix in BOTH layouts + per-(b,t) packed row minima.
// Each block: one 32-q tile x FOUR 32-t subtiles (t-group = 128 t's).
// Subtiles 2-4's logits label-gathers hit L1 (same 32 q-rows) -> ~1/4 the
// L2 gather traffic vs one-tile-per-block.
// ---------------------------------------------------------------------------
__global__ void __launch_bounds__(256)
cost_fused_kernel(const float* __restrict__ logits,
                  const float* __restrict__ pboxes,
                  const float* __restrict__ pcut,
                  const int*   __restrict__ tlab,
                  const float* __restrict__ tboxes,
                  const float* __restrict__ tcut,
                  float* __restrict__ out) {
    const int b  = blockIdx.z;
    const int q0 = blockIdx.y << 5;
    const int tbase = blockIdx.x << 7;      // 128 t's per block

    __shared__ float s_tb[4][32];
    __shared__ int   s_lab[32];
    __shared__ float s_tc[32];
    __shared__ float s_pb[4][32];
    __shared__ float s_pc[32], s_rm[32], s_rs[32];
    __shared__ float tile[32][33];
    __shared__ unsigned long long srow[32];

    const int tx = threadIdx.x, ty = threadIdx.y;
    const int tid = ty * 32 + tx;

    // stage q-side once per block
    if (tid < 32) {
        int q = q0 + tid;
        if (q < NQ) {
            const float* pb = pboxes + (((size_t)b * NQ + q) << 2);
            s_pb[0][tid] = pb[0]; s_pb[1][tid] = pb[1];
            s_pb[2][tid] = pb[2]; s_pb[3][tid] = pb[3];
        }
    } else if (tid < 64) {
        int l = tid - 32; int q = q0 + l;
        if (q < NQ) {
            s_pc[l] = pcut[b * NQ + q];
            s_rm[l] = g_rmax[b * NQ + q];
            s_rs[l] = g_rsum[b * NQ + q];
        }
    }

#pragma unroll
    for (int sub = 0; sub < 4; sub++) {
        const int t0 = tbase + (sub << 5);
        if (t0 >= NT) break;                // uniform across block

        __syncthreads();                    // prior drain done; s_* stable
        if (ty == 0) srow[tx] = ~0ULL;
        if (tid < 32) {
            int t = t0 + tid;
            if (t < NT) {
                const float* tb = tboxes + (((size_t)b * NT + t) << 2);
                s_tb[0][tid] = tb[0]; s_tb[1][tid] = tb[1];
                s_tb[2][tid] = tb[2]; s_tb[3][tid] = tb[3];
                s_lab[tid] = tlab[b * NT + t];
                s_tc[tid]  = tcut[b * NT + t];
            }
        }
        __syncthreads();

        const int t = t0 + tx;
        const bool tvalid = t < NT;
        float tbx0 = s_tb[0][tx], tby0 = s_tb[1][tx];
        float tbx1 = s_tb[2][tx], tby1 = s_tb[3][tx];
        int   lab  = tvalid ? s_lab[tx] : 0;
        float tcv  = s_tc[tx];
        float area_t = (tbx1 - tbx0) * (tby1 - tby0);

        unsigned long long lmin = ~0ULL;

#pragma unroll
        for (int r = 0; r < 4; r++) {
            int ql = ty + 8 * r;
            int q  = q0 + ql;
            float cost = 0.f;
            if (tvalid && q < NQ) {
                float px0 = s_pb[0][ql], py0 = s_pb[1][ql];
                float px1 = s_pb[2][ql], py1 = s_pb[3][ql];
                float logit = logits[((size_t)b * NQ + q) * NC + lab];
                float prob  = expf(logit - s_rm[ql]) / s_rs[ql];

                float cost_bbox = fabsf(px0 - tbx0) + fabsf(py0 - tby0) +
                                  fabsf(px1 - tbx1) + fabsf(py1 - tby1);
                float area_p = (px1 - px0) * (py1 - py0);
                float iw = fminf(px1, tbx1) - fmaxf(px0, tbx0);
                float ih = fminf(py1, tby1) - fmaxf(py0, tby0);
                float inter = fmaxf(iw, 0.f) * fmaxf(ih, 0.f);
                float uni = area_p + area_t - inter;
                float iou = inter / uni;
                float ew = fmaxf(px1, tbx1) - fminf(px0, tbx0);
                float eh = fmaxf(py1, tby1) - fminf(py0, tby0);
                float enc = fmaxf(ew, 0.f) * fmaxf(eh, 0.f);
                float giou = iou - (enc - uni) / enc;
                float ccut = fabsf(s_pc[ql] - tcv);

                cost = W_BBOX * cost_bbox - W_CLASS * prob
                     - W_GIOU * giou + W_CUTIN * ccut;
                out[((size_t)b * NQ + q) * NT + t] = cost;

                unsigned long long pk =
                    (unsigned long long)(f2fix(cost) * 2048LL + (long long)(q + 1)) + PBIAS;
                if (pk < lmin) lmin = pk;
            }
            tile[ql][tx] = cost;
        }
        if (lmin != ~0ULL) atomicMin(&srow[tx], lmin);
        __syncthreads();

        int q = q0 + tx;
#pragma unroll
        for (int r = 0; r < 4; r++) {
            int tl = ty + 8 * r;
            int t2 = t0 + tl;
            if (t2 < NT && q < NQ)
                g_CT[((size_t)b * NT + t2) * NQ + q] = tile[tx][tl];
        }
        if (ty == 0 && tvalid) atomicMin(&g_rowmin[b * NT + t], srow[tx]);
    }
}

// ---------------------------------------------------------------------------
// Kernel 3: parallel greedy + parallel auction rounds + exact int64 Dijkstra
// residue. One CTA/batch, 512 threads (16 warps) — byte-identical to the
// proven 147.5us version.
// ---------------------------------------------------------------------------
__global__ void __launch_bounds__(LSA_THREADS, 1)
lsa_kernel(float* __restrict__ outq, float* __restrict__ outt) {
    const int b = blockIdx.x;
    const int tid = threadIdx.x;
    const int warp = tid >> 5;
    const int lane = tid & 31;

    __shared__ long long u_s[NT + 1];
    __shared__ long long v_s[NQ + 1];
    __shared__ int p_s[NQ + 1];
    __shared__ int way_s[NQ + 1];
    __shared__ unsigned long long colslot[NQ + 1];
    __shared__ unsigned long long red[3][LSA_WARPS];
    __shared__ int flist[NT];
    __shared__ long long bid_d[NT], bid_u2[NT];
    __shared__ int bid_j[NT];
    __shared__ int amin[NT + 1];
    __shared__ int colclaim[NQ + 1];
    __shared__ int s_nf, s_live, s_nd;

    long long d[2];
    const int base = tid * 2 + 1;
    const bool owner = base <= NQ;          // tid < 450
    const long long INF = 1LL << 60;

    for (int j = tid; j <= NQ; j += LSA_THREADS) {
        p_s[j] = 0; v_s[j] = 0; colclaim[j] = 0x7fffffff;
    }
    for (int i = tid; i < NT; i += LSA_THREADS) {
        long long pk = (long long)(g_rowmin[b * NT + i] - PBIAS);
        u_s[i + 1] = pk >> 11;
        amin[i + 1] = (int)(pk & 2047);
    }
    if (tid < 3 * LSA_WARPS) red[tid / LSA_WARPS][tid % LSA_WARPS] = ~0ULL;
    if (tid == 0) { u_s[0] = 0; s_nf = 0; }
    __syncthreads();

    // ---- Phase 1: parallel greedy (column goes to smallest claiming row) ----
    for (int i = tid + 1; i <= NT; i += LSA_THREADS)
        atomicMin(&colclaim[amin[i]], i);
    __syncthreads();
    for (int i = tid + 1; i <= NT; i += LSA_THREADS) {
        int j = amin[i];
        if (colclaim[j] == i) p_s[j] = i;
        else flist[atomicAdd(&s_nf, 1)] = i;
    }
    __syncthreads();
    if (tid == 0) s_live = s_nf;
    __syncthreads();

    const float* __restrict__ Cb = g_CT + (size_t)b * NT * NQ;
    const int nf0 = s_nf;

    // ---- Phase 2: parallel auction rounds (batched ART) ----
    for (int round = 0; round < AUC_CAP; round++) {
        __syncthreads();
        if (s_live == 0) break;

        for (int j = tid; j <= NQ; j += LSA_THREADS) colslot[j] = ~0ULL;
        __syncthreads();

        for (int fi = warp; fi < nf0; fi += LSA_WARPS) {
            int row = flist[fi];
            if (row == 0) continue;
            const float* crow = Cb + (size_t)(row - 1) * NQ;

            unsigned long long t1 = ~0ULL, t2 = ~0ULL;
#pragma unroll
            for (int k = 0; k < 8; k++) {
                int f4 = lane + (k << 5);
                if (f4 < NQ / 4) {
                    float4 cf = reinterpret_cast<const float4*>(crow)[f4];
                    int col0 = f4 * 4 + 1;
                    long long ci[4] = {f2fix(cf.x), f2fix(cf.y),
                                       f2fix(cf.z), f2fix(cf.w)};
#pragma unroll
                    for (int c = 0; c < 4; c++) {
                        long long rc = ci[c] - v_s[col0 + c];
                        unsigned long long pk =
                            (unsigned long long)(rc * 2048LL +
                                                 (long long)(col0 + c)) + PBIAS;
                        if (pk < t1) { t2 = t1; t1 = pk; }
                        else if (pk < t2) t2 = pk;
                    }
                }
            }
#pragma unroll
            for (int o = 16; o; o >>= 1) {
                unsigned long long o1 = __shfl_down_sync(0xffffffffu, t1, o);
                unsigned long long o2 = __shfl_down_sync(0xffffffffu, t2, o);
                if (lane + o < 32) {
                    unsigned long long lo = t1 < o1 ? t1 : o1;
                    unsigned long long hi = t1 < o1 ? o1 : t1;
                    unsigned long long m2 = t2 < o2 ? t2 : o2;
                    t2 = hi < m2 ? hi : m2;
                    t1 = lo;
                }
            }
            if (lane == 0) {
                long long p1 = (long long)(t1 - PBIAS);
                long long p2 = (long long)(t2 - PBIAS);
                long long u1v = p1 >> 11, u2v = p2 >> 11;
                int j1 = (int)(p1 & 2047), j2 = (int)(p2 & 2047);
                long long delta = u2v - u1v;
                int jb = j1;
                if (delta == 0 && p_s[j1] != 0 && p_s[j2] == 0) jb = j2;
                bid_j[fi] = jb;
                bid_d[fi] = delta;
                bid_u2[fi] = u2v;
                unsigned long long key =
                    ((BIGKEY - (unsigned long long)delta) << 10) | (unsigned)fi;
                atomicMin(&colslot[jb], key);
            }
        }
        __syncthreads();

        for (int fi = tid; fi < nf0; fi += LSA_THREADS) {
            int row = flist[fi];
            if (row == 0) continue;
            int jb = bid_j[fi];
            if ((int)(colslot[jb] & 1023u) == fi) {
                int prev = p_s[jb];
                p_s[jb] = row;
                u_s[row] = bid_u2[fi];
                v_s[jb] -= bid_d[fi];
                if (prev > 0) flist[fi] = prev;
                else { flist[fi] = 0; atomicSub(&s_live, 1); }
            }
        }
    }
    __syncthreads();

    // gather residue for exact Dijkstra
    if (tid == 0) {
        int n = 0;
        for (int fi = 0; fi < nf0; fi++)
            if (flist[fi]) flist[n++] = flist[fi];
        s_nd = n;
    }
    __syncthreads();

    // ---- Phase 3: exact Dijkstra (shortest augmenting path) for residue ----
    const int nd = s_nd;
    int par = 0;
    for (int fi = 0; fi < nd; fi++) {
        d[0] = INF; d[1] = INF;
        unsigned usedm = 0;
        if (tid == 0) p_s[0] = flist[fi];
        __syncthreads();

        int j0 = 0;
        long long delta = 0;
        while (true) {
            int row = p_s[j0];
            long long k = delta - u_s[row];

            int rel = j0 - base;
            if (rel >= 0 && rel < 2) usedm |= 1u << rel;

            unsigned long long lmin = ~0ULL;
            if (owner) {
                float2 cf = *reinterpret_cast<const float2*>(
                    Cb + (size_t)(row - 1) * NQ + (base - 1));
                long long ci[2] = {f2fix(cf.x), f2fix(cf.y)};
#pragma unroll
                for (int c = 0; c < 2; c++) {
                    if (!((usedm >> c) & 1u)) {
                        long long alt = k + ci[c] - v_s[base + c];
                        if (alt < d[c]) { d[c] = alt; way_s[base + c] = j0; }
                        unsigned long long pk =
                            (unsigned long long)(d[c] * 2048LL +
                                                 (long long)(base + c)) + PBIAS;
                        if (pk < lmin) lmin = pk;
                    }
                }
            }
            int nxt = par + 1; if (nxt == 3) nxt = 0;
            if (lane == 0) red[nxt][warp] = ~0ULL;
            if (lmin != ~0ULL) atomicMin(&red[par][warp], lmin);
            __syncthreads();

            unsigned long long m = red[par][0];
#pragma unroll
            for (int w = 1; w < LSA_WARPS; w++) {
                unsigned long long x = red[par][w];
                if (x < m) m = x;
            }
            par = nxt;
            long long pks = (long long)(m - PBIAS);
            delta = pks >> 11;
            j0 = (int)(pks & 2047);
            if (p_s[j0] == 0) break;
        }

        const long long dstar = delta;
        if (owner) {
#pragma unroll
            for (int c = 0; c < 2; c++) {
                if ((usedm >> c) & 1u) {
                    v_s[base + c] += d[c] - dstar;
                    u_s[p_s[base + c]] += dstar - d[c];
                }
            }
        }
        if (tid == 0) u_s[p_s[0]] += dstar;
        __syncthreads();
        if (tid == 0) {
            int jj = j0;
            while (jj) { int j1 = way_s[jj]; p_s[jj] = p_s[j1]; jj = j1; }
        }
    }
    __syncthreads();

    for (int j = tid + 1; j <= NQ; j += LSA_THREADS) {
        int r = p_s[j];
        if (r > 0) outq[b * NT + (r - 1)] = (float)(j - 1);
    }
    for (int t = tid; t < NT; t += LSA_THREADS) outt[b * NT + t] = (float)t;
}

// ---------------------------------------------------------------------------
extern "C" void kernel_launch(void* const* d_in, const int* in_sizes, int n_in,
                              void* d_out, int out_size) {
    const float* logits = (const float*)d_in[0];
    const float* pboxes = (const float*)d_in[1];
    const float* pcut   = (const float*)d_in[2];
    const int*   tlab   = (const int*)d_in[3];
    const float* tboxes = (const float*)d_in[4];
    const float* tcut   = (const float*)d_in[5];
    float* out = (float*)d_out;

    int rows = NB * NQ;
    int threads = 256;
    int blocks = (rows * 32 + threads - 1) / threads;
    softmax_stats_kernel<<<blocks, threads>>>(logits);

    dim3 cgrid((NT + 127) / 128, (NQ + 31) / 32, NB);
    cost_fused_kernel<<<cgrid, dim3(32, 8)>>>(logits, pboxes, pcut, tlab,
                                              tboxes, tcut, out);

    float* outq = out + (size_t)NB * NQ * NT;
    float* outt = outq + (size_t)NB * NT;
    lsa_kernel<<<NB, LSA_THREADS>>>(outq, outt);
}

// round 15
// speedup vs baseline: 1.1041x; 1.1041x over previous
#include <cuda_runtime.h>
#include <math.h>
#include <float.h>

#define NB 32
#define NQ 900
#define NT 300
#define NC 256

#define W_CLASS 1.0f
#define W_BBOX  5.0f
#define W_GIOU  2.0f
#define W_CUTIN 2.0f

#define SCALE_F 17179869184.0f      // 2^34
#define PBIAS   (1ULL << 62)
#define BIGKEY  (1ULL << 45)
#define AUC_CAP 24
#define LSA_THREADS 512
#define LSA_WARPS   16
#define XP_BLOCKS   116             // transpose helper blocks (148 - 32)
#define TILES_PER_B 290             // 29 q-tiles * 10 t-tiles

// Scratch (allocation-free rule: __device__ globals)
__device__ float g_CT[(size_t)NB * NT * NQ];          // transposed cost [b][t][q]
__device__ float g_rmax[NB * NQ];
__device__ float g_rsum[NB * NQ];
__device__ unsigned long long g_rowmin[NB * NT];      // packed (fix<<11|col)+bias

__device__ __forceinline__ long long f2fix(float x) {
    return __float2ll_rn(x * SCALE_F);
}

// ---------------------------------------------------------------------------
// Kernel 1: softmax stats (max, sumexp) per (b,q). 1 warp/row, float4 loads.
// Also re-initializes g_rowmin every launch (graph replay safety).
// ---------------------------------------------------------------------------
__global__ void softmax_stats_kernel(const float* __restrict__ logits) {
    int gtid = blockIdx.x * blockDim.x + threadIdx.x;
    if (gtid < NB * NT) g_rowmin[gtid] = ~0ULL;

    int warp = gtid >> 5;
    int lane = threadIdx.x & 31;
    if (warp >= NB * NQ) return;
    const float4* row4 = reinterpret_cast<const float4*>(logits + (size_t)warp * NC);
    float4 a = row4[lane];
    float4 b = row4[lane + 32];
    float m = fmaxf(fmaxf(fmaxf(a.x, a.y), fmaxf(a.z, a.w)),
                    fmaxf(fmaxf(b.x, b.y), fmaxf(b.z, b.w)));
#pragma unroll
    for (int o = 16; o; o >>= 1) m = fmaxf(m, __shfl_xor_sync(0xffffffffu, m, o));
    float s = expf(a.x - m) + expf(a.y - m) + expf(a.z - m) + expf(a.w - m)
            + expf(b.x - m) + expf(b.y - m) + expf(b.z - m) + expf(b.w - m);
#pragma unroll
    for (int o = 16; o; o >>= 1) s += __shfl_xor_sync(0xffffffffu, s, o);
    if (lane == 0) { g_rmax[warp] = m; g_rsum[warp] = s; }
}

// ---------------------------------------------------------------------------
// Kernel 2: cost matrix -> g_CT ONLY (out[b][q][t] produced later, overlapped
// with the LSA). Same proven block structure as the 147.5us version, minus
// the out-store (stores halved: 69 -> 34.6 MB).
// ---------------------------------------------------------------------------
__global__ void __launch_bounds__(256)
cost_fused_kernel(const float* __restrict__ logits,
                  const float* __restrict__ pboxes,
                  const float* __restrict__ pcut,
                  const int*   __restrict__ tlab,
                  const float* __restrict__ tboxes,
                  const float* __restrict__ tcut) {
    int b = blockIdx.z;
    int t0 = blockIdx.x << 5;
    int q0 = blockIdx.y << 5;

    __shared__ float s_tb[4][32];
    __shared__ int   s_lab[32];
    __shared__ float s_tc[32];
    __shared__ float s_pb[4][32];
    __shared__ float s_pc[32], s_rm[32], s_rs[32];
    __shared__ float tile[32][33];
    __shared__ unsigned long long srow[32];

    int tx = threadIdx.x, ty = threadIdx.y;
    int tid = ty * 32 + tx;

    if (ty == 0) srow[tx] = ~0ULL;
    if (tid < 32) {
        int t = t0 + tid;
        if (t < NT) {
            const float* tb = tboxes + (((size_t)b * NT + t) << 2);
            s_tb[0][tid] = tb[0]; s_tb[1][tid] = tb[1];
            s_tb[2][tid] = tb[2]; s_tb[3][tid] = tb[3];
            s_lab[tid] = tlab[b * NT + t];
            s_tc[tid]  = tcut[b * NT + t];
        }
    } else if (tid < 64) {
        int l = tid - 32; int q = q0 + l;
        if (q < NQ) {
            const float* pb = pboxes + (((size_t)b * NQ + q) << 2);
            s_pb[0][l] = pb[0]; s_pb[1][l] = pb[1];
            s_pb[2][l] = pb[2]; s_pb[3][l] = pb[3];
        }
    } else if (tid < 96) {
        int l = tid - 64; int q = q0 + l;
        if (q < NQ) {
            s_pc[l] = pcut[b * NQ + q];
            s_rm[l] = g_rmax[b * NQ + q];
            s_rs[l] = g_rsum[b * NQ + q];
        }
    }
    __syncthreads();

    int t = t0 + tx;
    bool tvalid = t < NT;
    float tbx0 = s_tb[0][tx], tby0 = s_tb[1][tx];
    float tbx1 = s_tb[2][tx], tby1 = s_tb[3][tx];
    int   lab  = tvalid ? s_lab[tx] : 0;
    float tcv  = s_tc[tx];
    float area_t = (tbx1 - tbx0) * (tby1 - tby0);

    unsigned long long lmin = ~0ULL;

#pragma unroll
    for (int r = 0; r < 4; r++) {
        int ql = ty + 8 * r;
        int q  = q0 + ql;
        float cost = 0.f;
        if (tvalid && q < NQ) {
            float px0 = s_pb[0][ql], py0 = s_pb[1][ql];
            float px1 = s_pb[2][ql], py1 = s_pb[3][ql];
            float logit = logits[((size_t)b * NQ + q) * NC + lab];
            float prob  = expf(logit - s_rm[ql]) / s_rs[ql];

            float cost_bbox = fabsf(px0 - tbx0) + fabsf(py0 - tby0) +
                              fabsf(px1 - tbx1) + fabsf(py1 - tby1);
            float area_p = (px1 - px0) * (py1 - py0);
            float iw = fminf(px1, tbx1) - fmaxf(px0, tbx0);
            float ih = fminf(py1, tby1) - fmaxf(py0, tby0);
            float inter = fmaxf(iw, 0.f) * fmaxf(ih, 0.f);
            float uni = area_p + area_t - inter;
            float iou = inter / uni;
            float ew = fmaxf(px1, tbx1) - fminf(px0, tbx0);
            float eh = fmaxf(py1, tby1) - fminf(py0, tby0);
            float enc = fmaxf(ew, 0.f) * fmaxf(eh, 0.f);
            float giou = iou - (enc - uni) / enc;
            float ccut = fabsf(s_pc[ql] - tcv);

            cost = W_BBOX * cost_bbox - W_CLASS * prob
                 - W_GIOU * giou + W_CUTIN * ccut;

            unsigned long long pk =
                (unsigned long long)(f2fix(cost) * 2048LL + (long long)(q + 1)) + PBIAS;
            if (pk < lmin) lmin = pk;
        }
        tile[ql][tx] = cost;
    }
    if (lmin != ~0ULL) atomicMin(&srow[tx], lmin);
    __syncthreads();

    int q = q0 + tx;
#pragma unroll
    for (int r = 0; r < 4; r++) {
        int tl = ty + 8 * r;
        int t2 = t0 + tl;
        if (t2 < NT && q < NQ)
            g_CT[((size_t)b * NT + t2) * NQ + q] = tile[tx][tl];
    }
    if (ty == 0 && tvalid) atomicMin(&g_rowmin[b * NT + t], srow[tx]);
}

// ---------------------------------------------------------------------------
// Kernel 3 (hybrid): blocks 0..31 run the proven LSA (byte-identical logic);
// blocks 32..147 transpose g_CT[b][t][q] -> out[b][q][t] on otherwise-idle
// SMs, fully overlapped with the LSA. No inter-block dependency.
// ---------------------------------------------------------------------------
__global__ void __launch_bounds__(LSA_THREADS, 1)
lsa_kernel(float* __restrict__ out, float* __restrict__ outq,
           float* __restrict__ outt) {
    const int tid = threadIdx.x;

    // ===================== transpose helper blocks =====================
    if (blockIdx.x >= NB) {
        __shared__ float tt[32][33];
        const int tb = blockIdx.x - NB;
        const int tx = tid & 31;
        const int ty2 = tid >> 5;           // 0..15
        for (int tile = tb; tile < NB * TILES_PER_B; tile += XP_BLOCKS) {
            int b  = tile / TILES_PER_B;
            int r  = tile % TILES_PER_B;
            int q0 = (r / 10) << 5;
            int t0 = (r % 10) << 5;
#pragma unroll
            for (int h = 0; h < 2; h++) {
                int i = ty2 + 16 * h;       // t-local
                int t = t0 + i, qq = q0 + tx;
                if (t < NT && qq < NQ)
                    tt[i][tx] = g_CT[((size_t)b * NT + t) * NQ + qq];
            }
            __syncthreads();
#pragma unroll
            for (int h = 0; h < 2; h++) {
                int i = ty2 + 16 * h;       // q-local
                int qq = q0 + i, t = t0 + tx;
                if (qq < NQ && t < NT)
                    out[((size_t)b * NQ + qq) * NT + t] = tt[tx][i];
            }
            __syncthreads();
        }
        return;
    }

    // ============================ LSA blocks ===========================
    const int b = blockIdx.x;
    const int warp = tid >> 5;
    const int lane = tid & 31;

    __shared__ long long u_s[NT + 1];
    __shared__ long long v_s[NQ + 1];
    __shared__ int p_s[NQ + 1];
    __shared__ int way_s[NQ + 1];
    __shared__ unsigned long long colslot[NQ + 1];
    __shared__ unsigned long long red[3][LSA_WARPS];
    __shared__ int flist[NT];
    __shared__ long long bid_d[NT], bid_u2[NT];
    __shared__ int bid_j[NT];
    __shared__ int amin[NT + 1];
    __shared__ int colclaim[NQ + 1];
    __shared__ int s_nf, s_live, s_nd;

    long long d[2];
    const int base = tid * 2 + 1;
    const bool owner = base <= NQ;          // tid < 450
    const long long INF = 1LL << 60;

    for (int j = tid; j <= NQ; j += LSA_THREADS) {
        p_s[j] = 0; v_s[j] = 0; colclaim[j] = 0x7fffffff;
    }
    for (int i = tid; i < NT; i += LSA_THREADS) {
        long long pk = (long long)(g_rowmin[b * NT + i] - PBIAS);
        u_s[i + 1] = pk >> 11;
        amin[i + 1] = (int)(pk & 2047);
    }
    if (tid < 3 * LSA_WARPS) red[tid / LSA_WARPS][tid % LSA_WARPS] = ~0ULL;
    if (tid == 0) { u_s[0] = 0; s_nf = 0; }
    __syncthreads();

    // ---- Phase 1: parallel greedy (column goes to smallest claiming row) ----
    for (int i = tid + 1; i <= NT; i += LSA_THREADS)
        atomicMin(&colclaim[amin[i]], i);
    __syncthreads();
    for (int i = tid + 1; i <= NT; i += LSA_THREADS) {
        int j = amin[i];
        if (colclaim[j] == i) p_s[j] = i;
        else flist[atomicAdd(&s_nf, 1)] = i;
    }
    __syncthreads();
    if (tid == 0) s_live = s_nf;
    __syncthreads();

    const float* __restrict__ Cb = g_CT + (size_t)b * NT * NQ;
    const int nf0 = s_nf;

    // ---- Phase 2: parallel auction rounds (batched ART) ----
    for (int round = 0; round < AUC_CAP; round++) {
        __syncthreads();
        if (s_live == 0) break;

        for (int j = tid; j <= NQ; j += LSA_THREADS) colslot[j] = ~0ULL;
        __syncthreads();

        for (int fi = warp; fi < nf0; fi += LSA_WARPS) {
            int row = flist[fi];
            if (row == 0) continue;
            const float* crow = Cb + (size_t)(row - 1) * NQ;

            unsigned long long t1 = ~0ULL, t2 = ~0ULL;
#pragma unroll
            for (int k = 0; k < 8; k++) {
                int f4 = lane + (k << 5);
                if (f4 < NQ / 4) {
                    float4 cf = reinterpret_cast<const float4*>(crow)[f4];
                    int col0 = f4 * 4 + 1;
                    long long ci[4] = {f2fix(cf.x), f2fix(cf.y),
                                       f2fix(cf.z), f2fix(cf.w)};
#pragma unroll
                    for (int c = 0; c < 4; c++) {
                        long long rc = ci[c] - v_s[col0 + c];
                        unsigned long long pk =
                            (unsigned long long)(rc * 2048LL +
                                                 (long long)(col0 + c)) + PBIAS;
                        if (pk < t1) { t2 = t1; t1 = pk; }
                        else if (pk < t2) t2 = pk;
                    }
                }
            }
#pragma unroll
            for (int o = 16; o; o >>= 1) {
                unsigned long long o1 = __shfl_down_sync(0xffffffffu, t1, o);
                unsigned long long o2 = __shfl_down_sync(0xffffffffu, t2, o);
                if (lane + o < 32) {
                    unsigned long long lo = t1 < o1 ? t1 : o1;
                    unsigned long long hi = t1 < o1 ? o1 : t1;
                    unsigned long long m2 = t2 < o2 ? t2 : o2;
                    t2 = hi < m2 ? hi : m2;
                    t1 = lo;
                }
            }
            if (lane == 0) {
                long long p1 = (long long)(t1 - PBIAS);
                long long p2 = (long long)(t2 - PBIAS);
                long long u1v = p1 >> 11, u2v = p2 >> 11;
                int j1 = (int)(p1 & 2047), j2 = (int)(p2 & 2047);
                long long delta = u2v - u1v;
                int jb = j1;
                if (delta == 0 && p_s[j1] != 0 && p_s[j2] == 0) jb = j2;
                bid_j[fi] = jb;
                bid_d[fi] = delta;
                bid_u2[fi] = u2v;
                unsigned long long key =
                    ((BIGKEY - (unsigned long long)delta) << 10) | (unsigned)fi;
                atomicMin(&colslot[jb], key);
            }
        }
        __syncthreads();

        for (int fi = tid; fi < nf0; fi += LSA_THREADS) {
            int row = flist[fi];
            if (row == 0) continue;
            int jb = bid_j[fi];
            if ((int)(colslot[jb] & 1023u) == fi) {
                int prev = p_s[jb];
                p_s[jb] = row;
                u_s[row] = bid_u2[fi];
                v_s[jb] -= bid_d[fi];
                if (prev > 0) flist[fi] = prev;
                else { flist[fi] = 0; atomicSub(&s_live, 1); }
            }
        }
    }
    __syncthreads();

    // gather residue for exact Dijkstra
    if (tid == 0) {
        int n = 0;
        for (int fi = 0; fi < nf0; fi++)
            if (flist[fi]) flist[n++] = flist[fi];
        s_nd = n;
    }
    __syncthreads();

    // ---- Phase 3: exact Dijkstra (shortest augmenting path) for residue ----
    const int nd = s_nd;
    int par = 0;
    for (int fi = 0; fi < nd; fi++) {
        d[0] = INF; d[1] = INF;
        unsigned usedm = 0;
        if (tid == 0) p_s[0] = flist[fi];
        __syncthreads();

        int j0 = 0;
        long long delta = 0;
        while (true) {
            int row = p_s[j0];
            long long k = delta - u_s[row];

            int rel = j0 - base;
            if (rel >= 0 && rel < 2) usedm |= 1u << rel;

            unsigned long long lmin = ~0ULL;
            if (owner) {
                float2 cf = *reinterpret_cast<const float2*>(
                    Cb + (size_t)(row - 1) * NQ + (base - 1));
                long long ci[2] = {f2fix(cf.x), f2fix(cf.y)};
#pragma unroll
                for (int c = 0; c < 2; c++) {
                    if (!((usedm >> c) & 1u)) {
                        long long alt = k + ci[c] - v_s[base + c];
                        if (alt < d[c]) { d[c] = alt; way_s[base + c] = j0; }
                        unsigned long long pk =
                            (unsigned long long)(d[c] * 2048LL +
                                                 (long long)(base + c)) + PBIAS;
                        if (pk < lmin) lmin = pk;
                    }
                }
            }
            int nxt = par + 1; if (nxt == 3) nxt = 0;
            if (lane == 0) red[nxt][warp] = ~0ULL;
            if (lmin != ~0ULL) atomicMin(&red[par][warp], lmin);
            __syncthreads();

            unsigned long long m = red[par][0];
#pragma unroll
            for (int w = 1; w < LSA_WARPS; w++) {
                unsigned long long x = red[par][w];
                if (x < m) m = x;
            }
            par = nxt;
            long long pks = (long long)(m - PBIAS);
            delta = pks >> 11;
            j0 = (int)(pks & 2047);
            if (p_s[j0] == 0) break;
        }

        const long long dstar = delta;
        if (owner) {
#pragma unroll
            for (int c = 0; c < 2; c++) {
                if ((usedm >> c) & 1u) {
                    v_s[base + c] += d[c] - dstar;
                    u_s[p_s[base + c]] += dstar - d[c];
                }
            }
        }
        if (tid == 0) u_s[p_s[0]] += dstar;
        __syncthreads();
        if (tid == 0) {
            int jj = j0;
            while (jj) { int j1 = way_s[jj]; p_s[jj] = p_s[j1]; jj = j1; }
        }
    }
    __syncthreads();

    for (int j = tid + 1; j <= NQ; j += LSA_THREADS) {
        int r = p_s[j];
        if (r > 0) outq[b * NT + (r - 1)] = (float)(j - 1);
    }
    for (int t = tid; t < NT; t += LSA_THREADS) outt[b * NT + t] = (float)t;
}

// ---------------------------------------------------------------------------
extern "C" void kernel_launch(void* const* d_in, const int* in_sizes, int n_in,
                              void* d_out, int out_size) {
    const float* logits = (const float*)d_in[0];
    const float* pboxes = (const float*)d_in[1];
    const float* pcut   = (const float*)d_in[2];
    const int*   tlab   = (const int*)d_in[3];
    const float* tboxes = (const float*)d_in[4];
    const float* tcut   = (const float*)d_in[5];
    float* out = (float*)d_out;

    int rows = NB * NQ;
    int threads = 256;
    int blocks = (rows * 32 + threads - 1) / threads;
    softmax_stats_kernel<<<blocks, threads>>>(logits);

    dim3 cgrid((NT + 31) / 32, (NQ + 31) / 32, NB);
    cost_fused_kernel<<<cgrid, dim3(32, 8)>>>(logits, pboxes, pcut, tlab,
                                              tboxes, tcut);

    float* outq = out + (size_t)NB * NQ * NT;
    float* outt = outq + (size_t)NB * NT;
    lsa_kernel<<<NB + XP_BLOCKS, LSA_THREADS>>>(out, outq, outt);
}